// round 2
// baseline (speedup 1.0000x reference)
#include <cuda_runtime.h>
#include <math.h>

// SpatialGRU wavefront implementation (fp32 baseline).
// B=128, C=32, L=R=80, U=128, D=C+3U=416.
// Recurrence: cell(l,r) needs h(l,r-1) [left], h(l-1,r) [top], h(l-1,r-1) [diag].
// Anti-diagonal wavefront: one kernel launch per diagonal d=l+r (159 launches).
// Per-cell math fused into one 1024x416 GEMM (Wr|Wz|[0,Wij]) + one 128x384 GEMM (WU).

namespace {
constexpr int B = 128, C = 32, L = 80, R = 80, U = 128;
constexpr int D = 416;       // C + 3U (q = [h_top, h_left, h_diag, s])
constexpr int NGATE = 1024;  // 3U (r) + 4U (z) + U (s@Wij)
constexpr int MB = 32;       // batch rows per CTA (4 CTAs per cell)
constexpr int KB = 32;       // k-block staged to smem
constexpr int WSP = 44;      // smem W pitch (floats): conflict-free for lane-stride-1-row LDS.128

// shared memory layout (in floats)
constexpr int SM_A  = 0;                  // sA  [MB][D]       : 13312
constexpr int SM_W  = SM_A + MB * D;      // sW  [256][WSP]    : 11264
constexpr int SM_RT = SM_W + 256 * WSP;   // sRt [MB][384]     : 12288  (r * h_cat)
constexpr int SM_Z  = SM_RT + MB * 384;   // sZ  [4][MB][128]  : 16384  (z logits)
constexpr int SM_P  = SM_Z + 4 * MB * 128;// sP  [MB][128]     : 4096   (s@Wij + bij)
constexpr int SM_FLOATS = SM_P + MB * 128;         // 57344 floats = 229376 B
}

__device__ float g_W[NGATE * D];   // fused gate weights
__device__ float g_b[NGATE];       // fused gate bias
__device__ float g_x[L * R * B * C]; // transposed inputs (l,r,b,c)
__device__ float g_H[3][L][B * U];   // rotating diagonal h buffers, indexed by l

// ---------------------------------------------------------------------------
// Build fused weight matrix: rows 0..383 = Wr, 384..895 = Wz,
// rows 896..1023 = [zeros(384) | Wij] so chunk 7 of the gates GEMM emits s@Wij^T.
__global__ void prep_kernel(const float* __restrict__ Wr, const float* __restrict__ br,
                            const float* __restrict__ Wz, const float* __restrict__ bz,
                            const float* __restrict__ Wij, const float* __restrict__ bij) {
    int stride = gridDim.x * blockDim.x;
    int idx0 = blockIdx.x * blockDim.x + threadIdx.x;
    for (int i = idx0; i < NGATE * D; i += stride) {
        int j = i / D, k = i - j * D;
        float v;
        if (j < 384)      v = Wr[j * D + k];
        else if (j < 896) v = Wz[(j - 384) * D + k];
        else              v = (k >= 384) ? Wij[(j - 896) * C + (k - 384)] : 0.0f;
        g_W[i] = v;
    }
    for (int i = idx0; i < NGATE; i += stride)
        g_b[i] = (i < 384) ? br[i] : (i < 896 ? bz[i - 384] : bij[i - 896]);
}

// ---------------------------------------------------------------------------
// (B,C,L,R) -> (L,R,B,C) so each cell's s-tile is contiguous per batch row.
__global__ void transpose_kernel(const float* __restrict__ in) {
    __shared__ float tile[C][R + 1];
    int b = blockIdx.x, l = blockIdx.y;
    for (int i = threadIdx.x; i < C * R; i += blockDim.x) {
        int c = i / R, r = i - c * R;
        tile[c][r] = in[((b * C + c) * L + l) * R + r];
    }
    __syncthreads();
    for (int i = threadIdx.x; i < R * C; i += blockDim.x) {
        int r = i >> 5, c = i & 31;
        g_x[((l * R + r) * B + b) * C + c] = tile[c][r];
    }
}

// ---------------------------------------------------------------------------
// One CTA = (cell on diagonal d, 32-row batch tile).
// Stage 1: gates[32][1024] = [hT|hL|hD|s] @ g_W^T + g_b   (4 chunks of 256 cols)
// Stage 2: hU[32][128] = (r .* h_cat) @ WU^T, then h_hat, softmax combine, write h.
__global__ void __launch_bounds__(256, 1)
cell_kernel(int d, int lmin, const float* __restrict__ WU) {
    extern __shared__ float sm[];
    float* sA  = sm + SM_A;
    float* sW  = sm + SM_W;
    float* sRt = sm + SM_RT;
    float* sZ  = sm + SM_Z;
    float* sP  = sm + SM_P;

    const int cell = blockIdx.x >> 2;
    const int bt   = blockIdx.x & 3;
    const int l = lmin + cell;
    const int r = d - l;
    const int bs = bt * MB;

    const int tid = threadIdx.x;
    const int tj = tid & 31;   // lane: j within group (also warp lane)
    const int tb = tid >> 5;   // warp: which 4-row batch group

    // diag buffer rotation: d-1 -> (d+2)%3, d-2 -> (d+1)%3, write -> d%3
    const float* hT = (l > 0)          ? g_H[(d + 2) % 3][l - 1] : (const float*)nullptr;
    const float* hL = (r > 0)          ? g_H[(d + 2) % 3][l]     : (const float*)nullptr;
    const float* hD = (l > 0 && r > 0) ? g_H[(d + 1) % 3][l - 1] : (const float*)nullptr;
    float* Hout = g_H[d % 3][l];

    // Load A tile: q layout cols [0:128)=h_top, [128:256)=h_left, [256:384)=h_diag, [384:416)=s
    for (int i = tid; i < MB * U; i += 256) {
        int b = i >> 7, u = i & 127;
        int gi = (bs + b) * U + u;
        sA[b * D + u]       = hT ? hT[gi] : 0.0f;
        sA[b * D + 128 + u] = hL ? hL[gi] : 0.0f;
        sA[b * D + 256 + u] = hD ? hD[gi] : 0.0f;
    }
    for (int i = tid; i < MB * C; i += 256) {
        int b = i >> 5, c = i & 31;
        sA[b * D + 384 + c] = g_x[((l * R + r) * B + (bs + b)) * C + c];
    }
    // first __syncthreads inside the k-block loop covers these writes

    // ---- Stage 1 ----
    for (int ch = 0; ch < 4; ++ch) {
        float acc[4][8];
        #pragma unroll
        for (int bb = 0; bb < 4; ++bb)
            #pragma unroll
            for (int jj = 0; jj < 8; ++jj) acc[bb][jj] = 0.0f;
        const int jbase = ch * 256;

        for (int kb = 0; kb < D; kb += KB) {
            __syncthreads();
            // stage W block [jbase..jbase+255][kb..kb+31] into sW
            #pragma unroll
            for (int p = 0; p < 8; ++p) {
                int row = (tid >> 3) + p * 32;
                int kq  = (tid & 7) * 4;
                float4 wv = *(const float4*)&g_W[(jbase + row) * D + kb + kq];
                *(float4*)&sW[row * WSP + kq] = wv;
            }
            __syncthreads();
            #pragma unroll
            for (int kq = 0; kq < KB; kq += 4) {
                float4 a[4];
                #pragma unroll
                for (int bb = 0; bb < 4; ++bb)
                    a[bb] = *(const float4*)&sA[(tb * 4 + bb) * D + kb + kq];
                float4 w[8];
                #pragma unroll
                for (int jj = 0; jj < 8; ++jj)
                    w[jj] = *(const float4*)&sW[(jj * 32 + tj) * WSP + kq];
                #pragma unroll
                for (int bb = 0; bb < 4; ++bb)
                    #pragma unroll
                    for (int jj = 0; jj < 8; ++jj) {
                        acc[bb][jj] += a[bb].x * w[jj].x;
                        acc[bb][jj] += a[bb].y * w[jj].y;
                        acc[bb][jj] += a[bb].z * w[jj].z;
                        acc[bb][jj] += a[bb].w * w[jj].w;
                    }
            }
        }
        // activation / scatter
        #pragma unroll
        for (int bb = 0; bb < 4; ++bb) {
            int b = tb * 4 + bb;
            #pragma unroll
            for (int jj = 0; jj < 8; ++jj) {
                int j = jbase + jj * 32 + tj;
                float v = acc[bb][jj] + g_b[j];
                if (j < 384) {
                    // r gate: r[:,0:128]*h_left, [128:256)*h_top, [256:384)*h_diag
                    float rg = 1.0f / (1.0f + expf(-v));
                    int u = j & 127;
                    int part = j >> 7;
                    int off = (part == 0) ? 128 : (part == 1 ? 0 : 256);
                    sRt[b * 384 + j] = rg * sA[b * D + off + u];
                } else if (j < 896) {
                    int jz = j - 384;  // group 0:zi 1:zl 2:zt 3:zd
                    sZ[((jz >> 7) * MB + b) * 128 + (jz & 127)] = v;
                } else {
                    sP[b * 128 + (j - 896)] = v;  // s@Wij^T + bij
                }
            }
        }
    }

    // ---- Stage 2: hU = sRt @ WU^T ----
    float acc2[4][4];
    #pragma unroll
    for (int bb = 0; bb < 4; ++bb)
        #pragma unroll
        for (int jj = 0; jj < 4; ++jj) acc2[bb][jj] = 0.0f;

    for (int kb = 0; kb < 384; kb += KB) {
        __syncthreads();   // also guards sRt writes before first read
        #pragma unroll
        for (int p = 0; p < 4; ++p) {
            int row = (tid >> 3) + p * 32;
            int kq  = (tid & 7) * 4;
            float4 wv = *(const float4*)&WU[row * 384 + kb + kq];
            *(float4*)&sW[row * WSP + kq] = wv;
        }
        __syncthreads();
        #pragma unroll
        for (int kq = 0; kq < KB; kq += 4) {
            float4 a[4];
            #pragma unroll
            for (int bb = 0; bb < 4; ++bb)
                a[bb] = *(const float4*)&sRt[(tb * 4 + bb) * 384 + kb + kq];
            float4 w[4];
            #pragma unroll
            for (int jj = 0; jj < 4; ++jj)
                w[jj] = *(const float4*)&sW[(jj * 32 + tj) * WSP + kq];
            #pragma unroll
            for (int bb = 0; bb < 4; ++bb)
                #pragma unroll
                for (int jj = 0; jj < 4; ++jj) {
                    acc2[bb][jj] += a[bb].x * w[jj].x;
                    acc2[bb][jj] += a[bb].y * w[jj].y;
                    acc2[bb][jj] += a[bb].z * w[jj].z;
                    acc2[bb][jj] += a[bb].w * w[jj].w;
                }
        }
    }

    // ---- finale: h_hat, softmax over {zi,zl,zt,zd}, combine, write ----
    #pragma unroll
    for (int bb = 0; bb < 4; ++bb) {
        int b = tb * 4 + bb;
        #pragma unroll
        for (int jj = 0; jj < 4; ++jj) {
            int u = jj * 32 + tj;
            float hhat = tanhf(sP[b * 128 + u] + acc2[bb][jj]);
            float zi = sZ[(0 * MB + b) * 128 + u];
            float zl = sZ[(1 * MB + b) * 128 + u];
            float zt = sZ[(2 * MB + b) * 128 + u];
            float zd = sZ[(3 * MB + b) * 128 + u];
            float m = fmaxf(fmaxf(zi, zl), fmaxf(zt, zd));
            float ei = expf(zi - m), el = expf(zl - m), et = expf(zt - m), ed = expf(zd - m);
            float hLv = sA[b * D + 128 + u];
            float hTv = sA[b * D + u];
            float hDv = sA[b * D + 256 + u];
            Hout[(bs + b) * U + u] =
                (ei * hhat + el * hLv + et * hTv + ed * hDv) / (ei + el + et + ed);
        }
    }
}

// ---------------------------------------------------------------------------
__global__ void out_kernel(float* __restrict__ out) {
    int i = blockIdx.x * blockDim.x + threadIdx.x;
    if (i < B * U) out[i] = g_H[(L + R - 2) % 3][L - 1][i];
}

extern "C" void kernel_launch(void* const* d_in, const int* in_sizes, int n_in,
                              void* d_out, int out_size) {
    const float* inputs = (const float*)d_in[0];
    const float* Wr  = (const float*)d_in[1];
    const float* br  = (const float*)d_in[2];
    const float* Wz  = (const float*)d_in[3];
    const float* bz  = (const float*)d_in[4];
    const float* Wij = (const float*)d_in[5];
    const float* bij = (const float*)d_in[6];
    const float* WU  = (const float*)d_in[7];

    cudaFuncSetAttribute(cell_kernel, cudaFuncAttributeMaxDynamicSharedMemorySize,
                         SM_FLOATS * (int)sizeof(float));

    prep_kernel<<<128, 256>>>(Wr, br, Wz, bz, Wij, bij);
    transpose_kernel<<<dim3(B, L), 256>>>(inputs);

    for (int d = 0; d < L + R - 1; ++d) {
        int lmin = d - (R - 1); if (lmin < 0) lmin = 0;
        int lmax = (d < L - 1) ? d : (L - 1);
        int n = lmax - lmin + 1;
        cell_kernel<<<n * 4, 256, SM_FLOATS * sizeof(float)>>>(d, lmin, WU);
    }
    out_kernel<<<64, 256>>>((float*)d_out);
}

// round 3
// speedup vs baseline: 1.0535x; 1.0535x over previous
#include <cuda_runtime.h>
#include <math.h>

// SpatialGRU wavefront implementation (fp32 baseline).
// B=128, C=32, L=R=80, U=128, D=C+3U=416.
// Recurrence: cell(l,r) needs h(l,r-1) [left], h(l-1,r) [top], h(l-1,r-1) [diag].
// Anti-diagonal wavefront: one kernel launch per diagonal d=l+r (159 launches).
// Per-cell math fused into one 1024x416 GEMM (Wr|Wz|[0,Wij]) + one 128x384 GEMM (WU).

namespace {
constexpr int B = 128, C = 32, L = 80, R = 80, U = 128;
constexpr int D = 416;       // C + 3U (q = [h_top, h_left, h_diag, s])
constexpr int NGATE = 1024;  // 3U (r) + 4U (z) + U (s@Wij)
constexpr int MB = 32;       // batch rows per CTA (4 CTAs per cell)
constexpr int KB = 32;       // k-block staged to smem
constexpr int WSP = 44;      // smem W pitch (floats): conflict-free for lane-stride-1-row LDS.128

// shared memory layout (in floats)
constexpr int SM_A  = 0;                  // sA  [MB][D]       : 13312
constexpr int SM_W  = SM_A + MB * D;      // sW  [256][WSP]    : 11264
constexpr int SM_RT = SM_W + 256 * WSP;   // sRt [MB][384]     : 12288  (r * h_cat)
constexpr int SM_Z  = SM_RT + MB * 384;   // sZ  [4][MB][128]  : 16384  (z logits)
constexpr int SM_P  = SM_Z + 4 * MB * 128;// sP  [MB][128]     : 4096   (s@Wij + bij)
constexpr int SM_FLOATS = SM_P + MB * 128;         // 57344 floats = 229376 B
}

__device__ float g_W[NGATE * D];   // fused gate weights
__device__ float g_b[NGATE];       // fused gate bias
__device__ float g_x[L * R * B * C]; // transposed inputs (l,r,b,c)
__device__ float g_H[3][L][B * U];   // rotating diagonal h buffers, indexed by l

// ---------------------------------------------------------------------------
// Build fused weight matrix: rows 0..383 = Wr, 384..895 = Wz,
// rows 896..1023 = [zeros(384) | Wij] so chunk 7 of the gates GEMM emits s@Wij^T.
__global__ void prep_kernel(const float* __restrict__ Wr, const float* __restrict__ br,
                            const float* __restrict__ Wz, const float* __restrict__ bz,
                            const float* __restrict__ Wij, const float* __restrict__ bij) {
    int stride = gridDim.x * blockDim.x;
    int idx0 = blockIdx.x * blockDim.x + threadIdx.x;
    for (int i = idx0; i < NGATE * D; i += stride) {
        int j = i / D, k = i - j * D;
        float v;
        if (j < 384)      v = Wr[j * D + k];
        else if (j < 896) v = Wz[(j - 384) * D + k];
        else              v = (k >= 384) ? Wij[(j - 896) * C + (k - 384)] : 0.0f;
        g_W[i] = v;
    }
    for (int i = idx0; i < NGATE; i += stride)
        g_b[i] = (i < 384) ? br[i] : (i < 896 ? bz[i - 384] : bij[i - 896]);
}

// ---------------------------------------------------------------------------
// (B,C,L,R) -> (L,R,B,C) so each cell's s-tile is contiguous per batch row.
__global__ void transpose_kernel(const float* __restrict__ in) {
    __shared__ float tile[C][R + 1];
    int b = blockIdx.x, l = blockIdx.y;
    for (int i = threadIdx.x; i < C * R; i += blockDim.x) {
        int c = i / R, r = i - c * R;
        tile[c][r] = in[((b * C + c) * L + l) * R + r];
    }
    __syncthreads();
    for (int i = threadIdx.x; i < R * C; i += blockDim.x) {
        int r = i >> 5, c = i & 31;
        g_x[((l * R + r) * B + b) * C + c] = tile[c][r];
    }
}

// ---------------------------------------------------------------------------
// One CTA = (cell on diagonal d, 32-row batch tile).
// Stage 1: gates[32][1024] = [hT|hL|hD|s] @ g_W^T + g_b   (4 chunks of 256 cols)
// Stage 2: hU[32][128] = (r .* h_cat) @ WU^T, then h_hat, softmax combine, write h.
__global__ void __launch_bounds__(256, 1)
cell_kernel(int d, int lmin, const float* __restrict__ WU) {
    extern __shared__ float sm[];
    float* sA  = sm + SM_A;
    float* sW  = sm + SM_W;
    float* sRt = sm + SM_RT;
    float* sZ  = sm + SM_Z;
    float* sP  = sm + SM_P;

    const int cell = blockIdx.x >> 2;
    const int bt   = blockIdx.x & 3;
    const int l = lmin + cell;
    const int r = d - l;
    const int bs = bt * MB;

    const int tid = threadIdx.x;
    const int tj = tid & 31;   // lane: j within group (also warp lane)
    const int tb = tid >> 5;   // warp: which 4-row batch group

    // diag buffer rotation: d-1 -> (d+2)%3, d-2 -> (d+1)%3, write -> d%3
    const float* hT = (l > 0)          ? g_H[(d + 2) % 3][l - 1] : (const float*)nullptr;
    const float* hL = (r > 0)          ? g_H[(d + 2) % 3][l]     : (const float*)nullptr;
    const float* hD = (l > 0 && r > 0) ? g_H[(d + 1) % 3][l - 1] : (const float*)nullptr;
    float* Hout = g_H[d % 3][l];

    // Load A tile: q layout cols [0:128)=h_top, [128:256)=h_left, [256:384)=h_diag, [384:416)=s
    for (int i = tid; i < MB * U; i += 256) {
        int b = i >> 7, u = i & 127;
        int gi = (bs + b) * U + u;
        sA[b * D + u]       = hT ? hT[gi] : 0.0f;
        sA[b * D + 128 + u] = hL ? hL[gi] : 0.0f;
        sA[b * D + 256 + u] = hD ? hD[gi] : 0.0f;
    }
    for (int i = tid; i < MB * C; i += 256) {
        int b = i >> 5, c = i & 31;
        sA[b * D + 384 + c] = g_x[((l * R + r) * B + (bs + b)) * C + c];
    }
    // first __syncthreads inside the k-block loop covers these writes

    // ---- Stage 1 ----
    for (int ch = 0; ch < 4; ++ch) {
        float acc[4][8];
        #pragma unroll
        for (int bb = 0; bb < 4; ++bb)
            #pragma unroll
            for (int jj = 0; jj < 8; ++jj) acc[bb][jj] = 0.0f;
        const int jbase = ch * 256;

        for (int kb = 0; kb < D; kb += KB) {
            __syncthreads();
            // stage W block [jbase..jbase+255][kb..kb+31] into sW
            #pragma unroll
            for (int p = 0; p < 8; ++p) {
                int row = (tid >> 3) + p * 32;
                int kq  = (tid & 7) * 4;
                float4 wv = *(const float4*)&g_W[(jbase + row) * D + kb + kq];
                *(float4*)&sW[row * WSP + kq] = wv;
            }
            __syncthreads();
            #pragma unroll
            for (int kq = 0; kq < KB; kq += 4) {
                float4 a[4];
                #pragma unroll
                for (int bb = 0; bb < 4; ++bb)
                    a[bb] = *(const float4*)&sA[(tb * 4 + bb) * D + kb + kq];
                float4 w[8];
                #pragma unroll
                for (int jj = 0; jj < 8; ++jj)
                    w[jj] = *(const float4*)&sW[(jj * 32 + tj) * WSP + kq];
                #pragma unroll
                for (int bb = 0; bb < 4; ++bb)
                    #pragma unroll
                    for (int jj = 0; jj < 8; ++jj) {
                        acc[bb][jj] += a[bb].x * w[jj].x;
                        acc[bb][jj] += a[bb].y * w[jj].y;
                        acc[bb][jj] += a[bb].z * w[jj].z;
                        acc[bb][jj] += a[bb].w * w[jj].w;
                    }
            }
        }
        // activation / scatter
        #pragma unroll
        for (int bb = 0; bb < 4; ++bb) {
            int b = tb * 4 + bb;
            #pragma unroll
            for (int jj = 0; jj < 8; ++jj) {
                int j = jbase + jj * 32 + tj;
                float v = acc[bb][jj] + g_b[j];
                if (j < 384) {
                    // r gate: r[:,0:128]*h_left, [128:256)*h_top, [256:384)*h_diag
                    float rg = 1.0f / (1.0f + expf(-v));
                    int u = j & 127;
                    int part = j >> 7;
                    int off = (part == 0) ? 128 : (part == 1 ? 0 : 256);
                    sRt[b * 384 + j] = rg * sA[b * D + off + u];
                } else if (j < 896) {
                    int jz = j - 384;  // group 0:zi 1:zl 2:zt 3:zd
                    sZ[((jz >> 7) * MB + b) * 128 + (jz & 127)] = v;
                } else {
                    sP[b * 128 + (j - 896)] = v;  // s@Wij^T + bij
                }
            }
        }
    }

    // ---- Stage 2: hU = sRt @ WU^T ----
    float acc2[4][4];
    #pragma unroll
    for (int bb = 0; bb < 4; ++bb)
        #pragma unroll
        for (int jj = 0; jj < 4; ++jj) acc2[bb][jj] = 0.0f;

    for (int kb = 0; kb < 384; kb += KB) {
        __syncthreads();   // also guards sRt writes before first read
        #pragma unroll
        for (int p = 0; p < 4; ++p) {
            int row = (tid >> 3) + p * 32;
            int kq  = (tid & 7) * 4;
            float4 wv = *(const float4*)&WU[row * 384 + kb + kq];
            *(float4*)&sW[row * WSP + kq] = wv;
        }
        __syncthreads();
        #pragma unroll
        for (int kq = 0; kq < KB; kq += 4) {
            float4 a[4];
            #pragma unroll
            for (int bb = 0; bb < 4; ++bb)
                a[bb] = *(const float4*)&sRt[(tb * 4 + bb) * 384 + kb + kq];
            float4 w[4];
            #pragma unroll
            for (int jj = 0; jj < 4; ++jj)
                w[jj] = *(const float4*)&sW[(jj * 32 + tj) * WSP + kq];
            #pragma unroll
            for (int bb = 0; bb < 4; ++bb)
                #pragma unroll
                for (int jj = 0; jj < 4; ++jj) {
                    acc2[bb][jj] += a[bb].x * w[jj].x;
                    acc2[bb][jj] += a[bb].y * w[jj].y;
                    acc2[bb][jj] += a[bb].z * w[jj].z;
                    acc2[bb][jj] += a[bb].w * w[jj].w;
                }
        }
    }

    // ---- finale: h_hat, softmax over {zi,zl,zt,zd}, combine, write ----
    #pragma unroll
    for (int bb = 0; bb < 4; ++bb) {
        int b = tb * 4 + bb;
        #pragma unroll
        for (int jj = 0; jj < 4; ++jj) {
            int u = jj * 32 + tj;
            float hhat = tanhf(sP[b * 128 + u] + acc2[bb][jj]);
            float zi = sZ[(0 * MB + b) * 128 + u];
            float zl = sZ[(1 * MB + b) * 128 + u];
            float zt = sZ[(2 * MB + b) * 128 + u];
            float zd = sZ[(3 * MB + b) * 128 + u];
            float m = fmaxf(fmaxf(zi, zl), fmaxf(zt, zd));
            float ei = expf(zi - m), el = expf(zl - m), et = expf(zt - m), ed = expf(zd - m);
            float hLv = sA[b * D + 128 + u];
            float hTv = sA[b * D + u];
            float hDv = sA[b * D + 256 + u];
            Hout[(bs + b) * U + u] =
                (ei * hhat + el * hLv + et * hTv + ed * hDv) / (ei + el + et + ed);
        }
    }
}

// ---------------------------------------------------------------------------
__global__ void out_kernel(float* __restrict__ out) {
    int i = blockIdx.x * blockDim.x + threadIdx.x;
    if (i < B * U) out[i] = g_H[(L + R - 2) % 3][L - 1][i];
}

extern "C" void kernel_launch(void* const* d_in, const int* in_sizes, int n_in,
                              void* d_out, int out_size) {
    const float* inputs = (const float*)d_in[0];
    const float* Wr  = (const float*)d_in[1];
    const float* br  = (const float*)d_in[2];
    const float* Wz  = (const float*)d_in[3];
    const float* bz  = (const float*)d_in[4];
    const float* Wij = (const float*)d_in[5];
    const float* bij = (const float*)d_in[6];
    const float* WU  = (const float*)d_in[7];

    cudaFuncSetAttribute(cell_kernel, cudaFuncAttributeMaxDynamicSharedMemorySize,
                         SM_FLOATS * (int)sizeof(float));

    prep_kernel<<<128, 256>>>(Wr, br, Wz, bz, Wij, bij);
    transpose_kernel<<<dim3(B, L), 256>>>(inputs);

    for (int d = 0; d < L + R - 1; ++d) {
        int lmin = d - (R - 1); if (lmin < 0) lmin = 0;
        int lmax = (d < L - 1) ? d : (L - 1);
        int n = lmax - lmin + 1;
        cell_kernel<<<n * 4, 256, SM_FLOATS * sizeof(float)>>>(d, lmin, WU);
    }
    out_kernel<<<64, 256>>>((float*)d_out);
}

// round 4
// speedup vs baseline: 1.0536x; 1.0001x over previous
#include <cuda_runtime.h>
#include <math.h>

// SpatialGRU wavefront implementation (fp32 baseline).
// B=128, C=32, L=R=80, U=128, D=C+3U=416.
// Recurrence: cell(l,r) needs h(l,r-1) [left], h(l-1,r) [top], h(l-1,r-1) [diag].
// Anti-diagonal wavefront: one kernel launch per diagonal d=l+r (159 launches).
// Per-cell math fused into one 1024x416 GEMM (Wr|Wz|[0,Wij]) + one 128x384 GEMM (WU).

namespace {
constexpr int B = 128, C = 32, L = 80, R = 80, U = 128;
constexpr int D = 416;       // C + 3U (q = [h_top, h_left, h_diag, s])
constexpr int NGATE = 1024;  // 3U (r) + 4U (z) + U (s@Wij)
constexpr int MB = 32;       // batch rows per CTA (4 CTAs per cell)
constexpr int KB = 32;       // k-block staged to smem
constexpr int WSP = 44;      // smem W pitch (floats): conflict-free for lane-stride-1-row LDS.128

// shared memory layout (in floats)
constexpr int SM_A  = 0;                  // sA  [MB][D]       : 13312
constexpr int SM_W  = SM_A + MB * D;      // sW  [256][WSP]    : 11264
constexpr int SM_RT = SM_W + 256 * WSP;   // sRt [MB][384]     : 12288  (r * h_cat)
constexpr int SM_Z  = SM_RT + MB * 384;   // sZ  [4][MB][128]  : 16384  (z logits)
constexpr int SM_P  = SM_Z + 4 * MB * 128;// sP  [MB][128]     : 4096   (s@Wij + bij)
constexpr int SM_FLOATS = SM_P + MB * 128;         // 57344 floats = 229376 B
}

__device__ float g_W[NGATE * D];   // fused gate weights
__device__ float g_b[NGATE];       // fused gate bias
__device__ float g_x[L * R * B * C]; // transposed inputs (l,r,b,c)
__device__ float g_H[3][L][B * U];   // rotating diagonal h buffers, indexed by l

// ---------------------------------------------------------------------------
// Build fused weight matrix: rows 0..383 = Wr, 384..895 = Wz,
// rows 896..1023 = [zeros(384) | Wij] so chunk 7 of the gates GEMM emits s@Wij^T.
__global__ void prep_kernel(const float* __restrict__ Wr, const float* __restrict__ br,
                            const float* __restrict__ Wz, const float* __restrict__ bz,
                            const float* __restrict__ Wij, const float* __restrict__ bij) {
    int stride = gridDim.x * blockDim.x;
    int idx0 = blockIdx.x * blockDim.x + threadIdx.x;
    for (int i = idx0; i < NGATE * D; i += stride) {
        int j = i / D, k = i - j * D;
        float v;
        if (j < 384)      v = Wr[j * D + k];
        else if (j < 896) v = Wz[(j - 384) * D + k];
        else              v = (k >= 384) ? Wij[(j - 896) * C + (k - 384)] : 0.0f;
        g_W[i] = v;
    }
    for (int i = idx0; i < NGATE; i += stride)
        g_b[i] = (i < 384) ? br[i] : (i < 896 ? bz[i - 384] : bij[i - 896]);
}

// ---------------------------------------------------------------------------
// (B,C,L,R) -> (L,R,B,C) so each cell's s-tile is contiguous per batch row.
__global__ void transpose_kernel(const float* __restrict__ in) {
    __shared__ float tile[C][R + 1];
    int b = blockIdx.x, l = blockIdx.y;
    for (int i = threadIdx.x; i < C * R; i += blockDim.x) {
        int c = i / R, r = i - c * R;
        tile[c][r] = in[((b * C + c) * L + l) * R + r];
    }
    __syncthreads();
    for (int i = threadIdx.x; i < R * C; i += blockDim.x) {
        int r = i >> 5, c = i & 31;
        g_x[((l * R + r) * B + b) * C + c] = tile[c][r];
    }
}

// ---------------------------------------------------------------------------
// One CTA = (cell on diagonal d, 32-row batch tile).
// Stage 1: gates[32][1024] = [hT|hL|hD|s] @ g_W^T + g_b   (4 chunks of 256 cols)
// Stage 2: hU[32][128] = (r .* h_cat) @ WU^T, then h_hat, softmax combine, write h.
__global__ void __launch_bounds__(256, 1)
cell_kernel(int d, int lmin, const float* __restrict__ WU) {
    extern __shared__ float sm[];
    float* sA  = sm + SM_A;
    float* sW  = sm + SM_W;
    float* sRt = sm + SM_RT;
    float* sZ  = sm + SM_Z;
    float* sP  = sm + SM_P;

    const int cell = blockIdx.x >> 2;
    const int bt   = blockIdx.x & 3;
    const int l = lmin + cell;
    const int r = d - l;
    const int bs = bt * MB;

    const int tid = threadIdx.x;
    const int tj = tid & 31;   // lane: j within group (also warp lane)
    const int tb = tid >> 5;   // warp: which 4-row batch group

    // diag buffer rotation: d-1 -> (d+2)%3, d-2 -> (d+1)%3, write -> d%3
    const float* hT = (l > 0)          ? g_H[(d + 2) % 3][l - 1] : (const float*)nullptr;
    const float* hL = (r > 0)          ? g_H[(d + 2) % 3][l]     : (const float*)nullptr;
    const float* hD = (l > 0 && r > 0) ? g_H[(d + 1) % 3][l - 1] : (const float*)nullptr;
    float* Hout = g_H[d % 3][l];

    // Load A tile: q layout cols [0:128)=h_top, [128:256)=h_left, [256:384)=h_diag, [384:416)=s
    for (int i = tid; i < MB * U; i += 256) {
        int b = i >> 7, u = i & 127;
        int gi = (bs + b) * U + u;
        sA[b * D + u]       = hT ? hT[gi] : 0.0f;
        sA[b * D + 128 + u] = hL ? hL[gi] : 0.0f;
        sA[b * D + 256 + u] = hD ? hD[gi] : 0.0f;
    }
    for (int i = tid; i < MB * C; i += 256) {
        int b = i >> 5, c = i & 31;
        sA[b * D + 384 + c] = g_x[((l * R + r) * B + (bs + b)) * C + c];
    }
    // first __syncthreads inside the k-block loop covers these writes

    // ---- Stage 1 ----
    for (int ch = 0; ch < 4; ++ch) {
        float acc[4][8];
        #pragma unroll
        for (int bb = 0; bb < 4; ++bb)
            #pragma unroll
            for (int jj = 0; jj < 8; ++jj) acc[bb][jj] = 0.0f;
        const int jbase = ch * 256;

        for (int kb = 0; kb < D; kb += KB) {
            __syncthreads();
            // stage W block [jbase..jbase+255][kb..kb+31] into sW
            #pragma unroll
            for (int p = 0; p < 8; ++p) {
                int row = (tid >> 3) + p * 32;
                int kq  = (tid & 7) * 4;
                float4 wv = *(const float4*)&g_W[(jbase + row) * D + kb + kq];
                *(float4*)&sW[row * WSP + kq] = wv;
            }
            __syncthreads();
            #pragma unroll
            for (int kq = 0; kq < KB; kq += 4) {
                float4 a[4];
                #pragma unroll
                for (int bb = 0; bb < 4; ++bb)
                    a[bb] = *(const float4*)&sA[(tb * 4 + bb) * D + kb + kq];
                float4 w[8];
                #pragma unroll
                for (int jj = 0; jj < 8; ++jj)
                    w[jj] = *(const float4*)&sW[(jj * 32 + tj) * WSP + kq];
                #pragma unroll
                for (int bb = 0; bb < 4; ++bb)
                    #pragma unroll
                    for (int jj = 0; jj < 8; ++jj) {
                        acc[bb][jj] += a[bb].x * w[jj].x;
                        acc[bb][jj] += a[bb].y * w[jj].y;
                        acc[bb][jj] += a[bb].z * w[jj].z;
                        acc[bb][jj] += a[bb].w * w[jj].w;
                    }
            }
        }
        // activation / scatter
        #pragma unroll
        for (int bb = 0; bb < 4; ++bb) {
            int b = tb * 4 + bb;
            #pragma unroll
            for (int jj = 0; jj < 8; ++jj) {
                int j = jbase + jj * 32 + tj;
                float v = acc[bb][jj] + g_b[j];
                if (j < 384) {
                    // r gate: r[:,0:128]*h_left, [128:256)*h_top, [256:384)*h_diag
                    float rg = 1.0f / (1.0f + expf(-v));
                    int u = j & 127;
                    int part = j >> 7;
                    int off = (part == 0) ? 128 : (part == 1 ? 0 : 256);
                    sRt[b * 384 + j] = rg * sA[b * D + off + u];
                } else if (j < 896) {
                    int jz = j - 384;  // group 0:zi 1:zl 2:zt 3:zd
                    sZ[((jz >> 7) * MB + b) * 128 + (jz & 127)] = v;
                } else {
                    sP[b * 128 + (j - 896)] = v;  // s@Wij^T + bij
                }
            }
        }
    }

    // ---- Stage 2: hU = sRt @ WU^T ----
    float acc2[4][4];
    #pragma unroll
    for (int bb = 0; bb < 4; ++bb)
        #pragma unroll
        for (int jj = 0; jj < 4; ++jj) acc2[bb][jj] = 0.0f;

    for (int kb = 0; kb < 384; kb += KB) {
        __syncthreads();   // also guards sRt writes before first read
        #pragma unroll
        for (int p = 0; p < 4; ++p) {
            int row = (tid >> 3) + p * 32;
            int kq  = (tid & 7) * 4;
            float4 wv = *(const float4*)&WU[row * 384 + kb + kq];
            *(float4*)&sW[row * WSP + kq] = wv;
        }
        __syncthreads();
        #pragma unroll
        for (int kq = 0; kq < KB; kq += 4) {
            float4 a[4];
            #pragma unroll
            for (int bb = 0; bb < 4; ++bb)
                a[bb] = *(const float4*)&sRt[(tb * 4 + bb) * 384 + kb + kq];
            float4 w[4];
            #pragma unroll
            for (int jj = 0; jj < 4; ++jj)
                w[jj] = *(const float4*)&sW[(jj * 32 + tj) * WSP + kq];
            #pragma unroll
            for (int bb = 0; bb < 4; ++bb)
                #pragma unroll
                for (int jj = 0; jj < 4; ++jj) {
                    acc2[bb][jj] += a[bb].x * w[jj].x;
                    acc2[bb][jj] += a[bb].y * w[jj].y;
                    acc2[bb][jj] += a[bb].z * w[jj].z;
                    acc2[bb][jj] += a[bb].w * w[jj].w;
                }
        }
    }

    // ---- finale: h_hat, softmax over {zi,zl,zt,zd}, combine, write ----
    #pragma unroll
    for (int bb = 0; bb < 4; ++bb) {
        int b = tb * 4 + bb;
        #pragma unroll
        for (int jj = 0; jj < 4; ++jj) {
            int u = jj * 32 + tj;
            float hhat = tanhf(sP[b * 128 + u] + acc2[bb][jj]);
            float zi = sZ[(0 * MB + b) * 128 + u];
            float zl = sZ[(1 * MB + b) * 128 + u];
            float zt = sZ[(2 * MB + b) * 128 + u];
            float zd = sZ[(3 * MB + b) * 128 + u];
            float m = fmaxf(fmaxf(zi, zl), fmaxf(zt, zd));
            float ei = expf(zi - m), el = expf(zl - m), et = expf(zt - m), ed = expf(zd - m);
            float hLv = sA[b * D + 128 + u];
            float hTv = sA[b * D + u];
            float hDv = sA[b * D + 256 + u];
            Hout[(bs + b) * U + u] =
                (ei * hhat + el * hLv + et * hTv + ed * hDv) / (ei + el + et + ed);
        }
    }
}

// ---------------------------------------------------------------------------
__global__ void out_kernel(float* __restrict__ out) {
    int i = blockIdx.x * blockDim.x + threadIdx.x;
    if (i < B * U) out[i] = g_H[(L + R - 2) % 3][L - 1][i];
}

extern "C" void kernel_launch(void* const* d_in, const int* in_sizes, int n_in,
                              void* d_out, int out_size) {
    const float* inputs = (const float*)d_in[0];
    const float* Wr  = (const float*)d_in[1];
    const float* br  = (const float*)d_in[2];
    const float* Wz  = (const float*)d_in[3];
    const float* bz  = (const float*)d_in[4];
    const float* Wij = (const float*)d_in[5];
    const float* bij = (const float*)d_in[6];
    const float* WU  = (const float*)d_in[7];

    cudaFuncSetAttribute(cell_kernel, cudaFuncAttributeMaxDynamicSharedMemorySize,
                         SM_FLOATS * (int)sizeof(float));

    prep_kernel<<<128, 256>>>(Wr, br, Wz, bz, Wij, bij);
    transpose_kernel<<<dim3(B, L), 256>>>(inputs);

    for (int d = 0; d < L + R - 1; ++d) {
        int lmin = d - (R - 1); if (lmin < 0) lmin = 0;
        int lmax = (d < L - 1) ? d : (L - 1);
        int n = lmax - lmin + 1;
        cell_kernel<<<n * 4, 256, SM_FLOATS * sizeof(float)>>>(d, lmin, WU);
    }
    out_kernel<<<64, 256>>>((float*)d_out);
}

// round 5
// speedup vs baseline: 1.4263x; 1.3537x over previous
#include <cuda_runtime.h>
#include <cuda_bf16.h>
#include <math.h>

// SpatialGRU wavefront, bf16x3 split-precision tensor-core version.
// B=128, C=32, L=R=80, U=128, D=C+3U=416.
// One launch per anti-diagonal (159). 4 CTAs per cell (32 batch rows each).
// Fused gate matrix rows reordered: [r(384) | p(128) | z(512)].
// GEMMs via mma.sync.m16n8k16 bf16 with A=Ahi+Alo, W=Whi+Wlo, fp32 accum:
//   acc += AhiWhi + AhiWlo + AloWhi   (error ~2^-16, recurrence stays fp32).

namespace {
constexpr int B = 128, C = 32, L = 80, R = 80, U = 128;
constexpr int D = 416;     // C + 3U
constexpr int NG = 1024;   // 384 r + 128 p + 512 z
constexpr int MB = 32;     // batch rows per CTA
constexpr int KP = 456;    // sA / sRt pitch in bf16 (912B: bank-conflict-free frags)
constexpr int WP = 40;     // sW pitch in bf16 (80B: conflict-free B-frag loads)
constexpr int KB = 32;     // k-block per smem stage

// shared memory layout (bytes)
constexpr int SM_AHI = 0;                      // [32][456] bf16 = 29184
constexpr int SM_ALO = SM_AHI + MB * KP * 2;
constexpr int SM_RT  = SM_ALO + MB * KP * 2;   // region: max(sRt hi+lo, sZ) = 65536
constexpr int SM_RTLO = SM_RT + MB * KP * 2;
constexpr int SM_W   = SM_RT + 65536;          // sWhi/sWlo [256][40] bf16 = 40960
constexpr int SM_WLO = SM_W + 256 * WP * 2;
constexpr int SM_P   = SM_W + 40960;           // fp32 [32][128] = 16384
constexpr int SM_BYTES = SM_P + MB * U * 4;    // 181248
}

__device__ __align__(128) __nv_bfloat16 g_Whi[NG * D];
__device__ __align__(128) __nv_bfloat16 g_Wlo[NG * D];
__device__ __align__(128) __nv_bfloat16 g_WUhi[U * 384];
__device__ __align__(128) __nv_bfloat16 g_WUlo[U * 384];
__device__ float g_bias[NG];
__device__ float g_x[L * R * B * C];   // (l,r,b,c)
__device__ float g_H[3][L][B * U];     // rotating diagonal h buffers

// ---------------------------------------------------------------------------
__global__ void prep_kernel(const float* __restrict__ Wr, const float* __restrict__ br,
                            const float* __restrict__ Wz, const float* __restrict__ bz,
                            const float* __restrict__ Wij, const float* __restrict__ bij,
                            const float* __restrict__ WU) {
    int idx0 = blockIdx.x * blockDim.x + threadIdx.x;
    int stride = gridDim.x * blockDim.x;
    for (int i = idx0; i < NG * D; i += stride) {
        int j = i / D, k = i - j * D;
        float v;
        if (j < 384)       v = Wr[j * D + k];
        else if (j < 512)  v = (k >= 384) ? Wij[(j - 384) * C + (k - 384)] : 0.0f;
        else               v = Wz[(j - 512) * D + k];
        __nv_bfloat16 h = __float2bfloat16(v);
        g_Whi[i] = h;
        g_Wlo[i] = __float2bfloat16(v - __bfloat162float(h));
    }
    for (int i = idx0; i < U * 384; i += stride) {
        float v = WU[i];
        __nv_bfloat16 h = __float2bfloat16(v);
        g_WUhi[i] = h;
        g_WUlo[i] = __float2bfloat16(v - __bfloat162float(h));
    }
    for (int i = idx0; i < NG; i += stride)
        g_bias[i] = (i < 384) ? br[i] : (i < 512 ? bij[i - 384] : bz[i - 512]);
}

// ---------------------------------------------------------------------------
__global__ void transpose_kernel(const float* __restrict__ in) {
    __shared__ float tile[C][R + 1];
    int b = blockIdx.x, l = blockIdx.y;
    for (int i = threadIdx.x; i < C * R; i += blockDim.x) {
        int c = i / R, r = i - c * R;
        tile[c][r] = in[((b * C + c) * L + l) * R + r];
    }
    __syncthreads();
    for (int i = threadIdx.x; i < R * C; i += blockDim.x) {
        int r = i >> 5, c = i & 31;
        g_x[((l * R + r) * B + b) * C + c] = tile[c][r];
    }
}

// ---------------------------------------------------------------------------
__device__ __forceinline__ void mma16816(float* c, const unsigned* a, const unsigned* b) {
    asm volatile(
        "mma.sync.aligned.m16n8k16.row.col.f32.bf16.bf16.f32 "
        "{%0,%1,%2,%3}, {%4,%5,%6,%7}, {%8,%9}, {%0,%1,%2,%3};"
        : "+f"(c[0]), "+f"(c[1]), "+f"(c[2]), "+f"(c[3])
        : "r"(a[0]), "r"(a[1]), "r"(a[2]), "r"(a[3]), "r"(b[0]), "r"(b[1]));
}

__device__ __forceinline__ void split_store(__nv_bfloat16* hi, __nv_bfloat16* lo, float v) {
    __nv_bfloat16 h = __float2bfloat16(v);
    *hi = h;
    *lo = __float2bfloat16(v - __bfloat162float(h));
}

// ---------------------------------------------------------------------------
__global__ void __launch_bounds__(256, 1)
cell_kernel(int d, int lmin) {
    extern __shared__ char sm[];
    __nv_bfloat16* sAhi  = (__nv_bfloat16*)(sm + SM_AHI);
    __nv_bfloat16* sAlo  = (__nv_bfloat16*)(sm + SM_ALO);
    __nv_bfloat16* sRthi = (__nv_bfloat16*)(sm + SM_RT);
    __nv_bfloat16* sRtlo = (__nv_bfloat16*)(sm + SM_RTLO);
    float*         sZ    = (float*)(sm + SM_RT);     // overlaps sRt (used after stage2)
    __nv_bfloat16* sWhi  = (__nv_bfloat16*)(sm + SM_W);
    __nv_bfloat16* sWlo  = (__nv_bfloat16*)(sm + SM_WLO);
    float*         sP    = (float*)(sm + SM_P);

    const int cell = blockIdx.x >> 2;
    const int bt   = blockIdx.x & 3;
    const int l = lmin + cell;
    const int r = d - l;
    const int bs = bt * MB;

    const int tid  = threadIdx.x;
    const int warp = tid >> 5;
    const int lane = tid & 31;
    const int g    = lane >> 2;   // group id (0..7)
    const int tig  = lane & 3;    // thread in group

    const float* hT = (l > 0)          ? g_H[(d + 2) % 3][l - 1] : (const float*)nullptr;
    const float* hL = (r > 0)          ? g_H[(d + 2) % 3][l]     : (const float*)nullptr;
    const float* hD = (l > 0 && r > 0) ? g_H[(d + 1) % 3][l - 1] : (const float*)nullptr;
    float* Hout = g_H[d % 3][l];

    // ---- init A tile (split to bf16 hi/lo): cols [0:128)=hT, [128:256)=hL,
    //      [256:384)=hD, [384:416)=s ----
    for (int i = tid; i < MB * D; i += 256) {
        int b = i / D, k = i - b * D;
        float v;
        if (k < 384) {
            int part = k >> 7, u = k & 127;
            const float* src = (part == 0) ? hT : (part == 1 ? hL : hD);
            v = src ? src[(bs + b) * U + u] : 0.0f;
        } else {
            v = g_x[((l * R + r) * B + (bs + b)) * C + (k - 384)];
        }
        split_store(&sAhi[b * KP + k], &sAlo[b * KP + k], v);
    }

    float hhat[16];

    // ---- 4 chunks of 256 gate cols; stage2 inserted before chunk 2 ----
    for (int ch = 0; ch < 4; ++ch) {

        if (ch == 2) {
            // ======== stage 2: hU = (r.*h) @ WU^T, h_hat = tanh(p + hU) ========
            float acc2[4][4];
            #pragma unroll
            for (int t = 0; t < 4; ++t)
                #pragma unroll
                for (int e = 0; e < 4; ++e) acc2[t][e] = 0.0f;

            for (int kb = 0; kb < 12; ++kb) {
                __syncthreads();
                #pragma unroll
                for (int rep = 0; rep < 2; ++rep) {
                    int idx = tid + rep * 256;        // 0..511
                    int row = idx >> 2, q = idx & 3;
                    *(uint4*)(sWhi + row * WP + q * 8) =
                        *(const uint4*)(g_WUhi + row * 384 + kb * KB + q * 8);
                    *(uint4*)(sWlo + row * WP + q * 8) =
                        *(const uint4*)(g_WUlo + row * 384 + kb * KB + q * 8);
                }
                __syncthreads();
                #pragma unroll
                for (int kk = 0; kk < 2; ++kk) {
                    int k0 = kb * KB + kk * 16;
                    unsigned ahi[2][4], alo[2][4];
                    #pragma unroll
                    for (int mi = 0; mi < 2; ++mi) {
                        int rb = (16 * mi + g) * KP + k0 + 2 * tig;
                        ahi[mi][0] = *(const unsigned*)(sRthi + rb);
                        ahi[mi][1] = *(const unsigned*)(sRthi + rb + 8 * KP);
                        ahi[mi][2] = *(const unsigned*)(sRthi + rb + 8);
                        ahi[mi][3] = *(const unsigned*)(sRthi + rb + 8 * KP + 8);
                        alo[mi][0] = *(const unsigned*)(sRtlo + rb);
                        alo[mi][1] = *(const unsigned*)(sRtlo + rb + 8 * KP);
                        alo[mi][2] = *(const unsigned*)(sRtlo + rb + 8);
                        alo[mi][3] = *(const unsigned*)(sRtlo + rb + 8 * KP + 8);
                    }
                    #pragma unroll
                    for (int ni = 0; ni < 2; ++ni) {
                        int rowb = (warp * 16 + ni * 8 + g) * WP + kk * 16 + 2 * tig;
                        unsigned bhi[2] = { *(const unsigned*)(sWhi + rowb),
                                            *(const unsigned*)(sWhi + rowb + 8) };
                        unsigned blo[2] = { *(const unsigned*)(sWlo + rowb),
                                            *(const unsigned*)(sWlo + rowb + 8) };
                        #pragma unroll
                        for (int mi = 0; mi < 2; ++mi) {
                            mma16816(acc2[mi * 2 + ni], ahi[mi], bhi);
                            mma16816(acc2[mi * 2 + ni], ahi[mi], blo);
                            mma16816(acc2[mi * 2 + ni], alo[mi], bhi);
                        }
                    }
                }
            }
            // h_hat into registers
            #pragma unroll
            for (int t = 0; t < 4; ++t) {
                int mi = t >> 1, ni = t & 1;
                #pragma unroll
                for (int e = 0; e < 4; ++e) {
                    int b = 16 * mi + g + ((e >> 1) << 3);
                    int u = warp * 16 + ni * 8 + 2 * tig + (e & 1);
                    hhat[t * 4 + e] = tanhf(sP[b * 128 + u] + acc2[t][e]);
                }
            }
        }

        // ======== stage 1 chunk: gates[:, jbase..jbase+255] ========
        float acc[8][4];
        #pragma unroll
        for (int t = 0; t < 8; ++t)
            #pragma unroll
            for (int e = 0; e < 4; ++e) acc[t][e] = 0.0f;
        const int jbase = ch * 256;

        for (int kb = 0; kb < 13; ++kb) {
            __syncthreads();
            #pragma unroll
            for (int rep = 0; rep < 4; ++rep) {
                int idx = tid + rep * 256;            // 0..1023
                int row = idx >> 2, q = idx & 3;
                *(uint4*)(sWhi + row * WP + q * 8) =
                    *(const uint4*)(g_Whi + (jbase + row) * D + kb * KB + q * 8);
                *(uint4*)(sWlo + row * WP + q * 8) =
                    *(const uint4*)(g_Wlo + (jbase + row) * D + kb * KB + q * 8);
            }
            __syncthreads();
            #pragma unroll
            for (int kk = 0; kk < 2; ++kk) {
                int k0 = kb * KB + kk * 16;
                unsigned ahi[2][4], alo[2][4];
                #pragma unroll
                for (int mi = 0; mi < 2; ++mi) {
                    int rb = (16 * mi + g) * KP + k0 + 2 * tig;
                    ahi[mi][0] = *(const unsigned*)(sAhi + rb);
                    ahi[mi][1] = *(const unsigned*)(sAhi + rb + 8 * KP);
                    ahi[mi][2] = *(const unsigned*)(sAhi + rb + 8);
                    ahi[mi][3] = *(const unsigned*)(sAhi + rb + 8 * KP + 8);
                    alo[mi][0] = *(const unsigned*)(sAlo + rb);
                    alo[mi][1] = *(const unsigned*)(sAlo + rb + 8 * KP);
                    alo[mi][2] = *(const unsigned*)(sAlo + rb + 8);
                    alo[mi][3] = *(const unsigned*)(sAlo + rb + 8 * KP + 8);
                }
                #pragma unroll
                for (int ni = 0; ni < 4; ++ni) {
                    int rowb = (warp * 32 + ni * 8 + g) * WP + kk * 16 + 2 * tig;
                    unsigned bhi[2] = { *(const unsigned*)(sWhi + rowb),
                                        *(const unsigned*)(sWhi + rowb + 8) };
                    unsigned blo[2] = { *(const unsigned*)(sWlo + rowb),
                                        *(const unsigned*)(sWlo + rowb + 8) };
                    #pragma unroll
                    for (int mi = 0; mi < 2; ++mi) {
                        mma16816(acc[mi * 4 + ni], ahi[mi], bhi);
                        mma16816(acc[mi * 4 + ni], ahi[mi], blo);
                        mma16816(acc[mi * 4 + ni], alo[mi], bhi);
                    }
                }
            }
        }

        // activation / scatter for this chunk
        #pragma unroll
        for (int t = 0; t < 8; ++t) {
            int mi = t >> 2, ni = t & 3;
            #pragma unroll
            for (int e = 0; e < 4; ++e) {
                int b = 16 * mi + g + ((e >> 1) << 3);
                int j = jbase + warp * 32 + ni * 8 + 2 * tig + (e & 1);
                float v = acc[t][e] + g_bias[j];
                if (j < 384) {
                    // r gate * h: cols [0:128)*h_left, [128:256)*h_top, [256:384)*h_diag
                    float rg = 1.0f / (1.0f + __expf(-v));
                    int u = j & 127, part = j >> 7;
                    int off = (part == 0) ? 128 : (part == 1 ? 0 : 256);
                    float hv = __bfloat162float(sAhi[b * KP + off + u]) +
                               __bfloat162float(sAlo[b * KP + off + u]);
                    split_store(&sRthi[b * KP + j], &sRtlo[b * KP + j], rg * hv);
                } else if (j < 512) {
                    sP[b * 128 + (j - 384)] = v;      // s@Wij^T + bij
                } else {
                    int jz = j - 512;
                    sZ[(((jz >> 7) * MB) + b) * 128 + (jz & 127)] = v;  // z logits
                }
            }
        }
    }

    // ---- finale: softmax over {zi,zl,zt,zd}, combine, write h ----
    __syncthreads();
    #pragma unroll
    for (int t = 0; t < 4; ++t) {
        int mi = t >> 1, ni = t & 1;
        #pragma unroll
        for (int e = 0; e < 4; ++e) {
            int b = 16 * mi + g + ((e >> 1) << 3);
            int u = warp * 16 + ni * 8 + 2 * tig + (e & 1);
            float zi = sZ[(0 * MB + b) * 128 + u];
            float zl = sZ[(1 * MB + b) * 128 + u];
            float zt = sZ[(2 * MB + b) * 128 + u];
            float zd = sZ[(3 * MB + b) * 128 + u];
            float m = fmaxf(fmaxf(zi, zl), fmaxf(zt, zd));
            float ei = __expf(zi - m), el = __expf(zl - m);
            float et = __expf(zt - m), ed = __expf(zd - m);
            int gi = (bs + b) * U + u;
            float hLv = hL ? hL[gi] : 0.0f;
            float hTv = hT ? hT[gi] : 0.0f;
            float hDv = hD ? hD[gi] : 0.0f;
            Hout[gi] = (ei * hhat[t * 4 + e] + el * hLv + et * hTv + ed * hDv) /
                       (ei + el + et + ed);
        }
    }
}

// ---------------------------------------------------------------------------
__global__ void out_kernel(float* __restrict__ out) {
    int i = blockIdx.x * blockDim.x + threadIdx.x;
    if (i < B * U) out[i] = g_H[(L + R - 2) % 3][L - 1][i];
}

extern "C" void kernel_launch(void* const* d_in, const int* in_sizes, int n_in,
                              void* d_out, int out_size) {
    const float* inputs = (const float*)d_in[0];
    const float* Wr  = (const float*)d_in[1];
    const float* br  = (const float*)d_in[2];
    const float* Wz  = (const float*)d_in[3];
    const float* bz  = (const float*)d_in[4];
    const float* Wij = (const float*)d_in[5];
    const float* bij = (const float*)d_in[6];
    const float* WU  = (const float*)d_in[7];

    cudaFuncSetAttribute(cell_kernel, cudaFuncAttributeMaxDynamicSharedMemorySize,
                         SM_BYTES);

    prep_kernel<<<128, 256>>>(Wr, br, Wz, bz, Wij, bij, WU);
    transpose_kernel<<<dim3(B, L), 256>>>(inputs);

    for (int d = 0; d < L + R - 1; ++d) {
        int lmin = d - (R - 1); if (lmin < 0) lmin = 0;
        int lmax = (d < L - 1) ? d : (L - 1);
        int n = lmax - lmin + 1;
        cell_kernel<<<n * 4, 256, SM_BYTES>>>(d, lmin);
    }
    out_kernel<<<64, 256>>>((float*)d_out);
}

// round 9
// speedup vs baseline: 2.5239x; 1.7695x over previous
#include <cuda_runtime.h>
#include <cuda_bf16.h>
#include <math.h>

// SpatialGRU wavefront, R6: split-phase (gates / combine) per diagonal,
// cp.async double-buffered bf16x3 mma.sync GEMMs, pre-packed split-A buffers.
// B=128, C=32, L=R=80, U=128, D=416, gates NG=1024 ordered [r(384)|p(128)|z(512)].

namespace {
constexpr int B = 128, C = 32, L = 80, R = 80, U = 128;
constexpr int D = 416;
constexpr int NG = 1024;
constexpr int BP = 40;                 // smem block pitch (bf16) -> conflict-free frags
// K1 stage layout (bf16 elements): Ahi[64][40] Alo Whi[128][40] Wlo
constexpr int K1_A = 64 * BP;          // 2560
constexpr int K1_W = 128 * BP;         // 5120
constexpr int K1_ST = 2 * K1_A + 2 * K1_W;   // 15360 el per stage
constexpr int K1_SMEM = 2 * K1_ST * 2;       // 61440 B
// K2 stage layout: RThi[32][40] RTlo WUhi[128][40] WUlo
constexpr int K2_RT = 32 * BP;         // 1280
constexpr int K2_W = 128 * BP;         // 5120
constexpr int K2_ST = 2 * K2_RT + 2 * K2_W;  // 12800 el
constexpr int K2_SMEM = 2 * K2_ST * 2;       // 51200 B
}

__device__ __align__(128) __nv_bfloat16 g_Whi[NG * D], g_Wlo[NG * D];
__device__ __align__(128) __nv_bfloat16 g_WUhi[U * 384], g_WUlo[U * 384];
__device__ float g_bias[NG];
__device__ __align__(128) __nv_bfloat16 g_shi[L * R * B * C], g_slo[L * R * B * C];
__device__ __align__(128) __nv_bfloat16 g_Ahi[3 * L * B * D], g_Alo[3 * L * B * D];
__device__ __align__(128) __nv_bfloat16 g_rthi[L * B * 384], g_rtlo[L * B * 384];
__device__ float g_zbuf[(size_t)L * 4 * B * U];
__device__ float g_pbuf[(size_t)L * B * U];
__device__ float g_H[3][L][B * U];

// ---------------------------------------------------------------------------
__device__ __forceinline__ void cpa(void* dst, const void* src) {
    unsigned s = (unsigned)__cvta_generic_to_shared(dst);
    asm volatile("cp.async.cg.shared.global [%0], [%1], 16;" :: "r"(s), "l"(src));
}
__device__ __forceinline__ void cp_commit() { asm volatile("cp.async.commit_group;"); }
template <int N> __device__ __forceinline__ void cp_wait() {
    asm volatile("cp.async.wait_group %0;" :: "n"(N));
}
__device__ __forceinline__ void mma16816(float* c, const unsigned* a, const unsigned* b) {
    asm volatile(
        "mma.sync.aligned.m16n8k16.row.col.f32.bf16.bf16.f32 "
        "{%0,%1,%2,%3}, {%4,%5,%6,%7}, {%8,%9}, {%0,%1,%2,%3};"
        : "+f"(c[0]), "+f"(c[1]), "+f"(c[2]), "+f"(c[3])
        : "r"(a[0]), "r"(a[1]), "r"(a[2]), "r"(a[3]), "r"(b[0]), "r"(b[1]));
}
__device__ __forceinline__ void split2(float v, __nv_bfloat16* hi, __nv_bfloat16* lo) {
    __nv_bfloat16 h = __float2bfloat16(v);
    *hi = h;
    *lo = __float2bfloat16(v - __bfloat162float(h));
}

// ---------------------------------------------------------------------------
__global__ void prep_kernel(const float* __restrict__ Wr, const float* __restrict__ br,
                            const float* __restrict__ Wz, const float* __restrict__ bz,
                            const float* __restrict__ Wij, const float* __restrict__ bij,
                            const float* __restrict__ WU) {
    int idx0 = blockIdx.x * blockDim.x + threadIdx.x;
    int stride = gridDim.x * blockDim.x;
    for (int i = idx0; i < NG * D; i += stride) {
        int j = i / D, k = i - j * D;
        float v;
        if (j < 384)      v = Wr[j * D + k];
        else if (j < 512) v = (k >= 384) ? Wij[(j - 384) * C + (k - 384)] : 0.0f;
        else              v = Wz[(j - 512) * D + k];
        split2(v, &g_Whi[i], &g_Wlo[i]);
    }
    for (int i = idx0; i < U * 384; i += stride)
        split2(WU[i], &g_WUhi[i], &g_WUlo[i]);
    for (int i = idx0; i < NG; i += stride)
        g_bias[i] = (i < 384) ? br[i] : (i < 512 ? bij[i - 384] : bz[i - 512]);
}

__global__ void transpose_kernel(const float* __restrict__ in) {
    __shared__ float tile[C][R + 1];
    int b = blockIdx.x, l = blockIdx.y;
    for (int i = threadIdx.x; i < C * R; i += blockDim.x) {
        int c = i / R, r = i - c * R;
        tile[c][r] = in[((b * C + c) * L + l) * R + r];
    }
    __syncthreads();
    for (int i = threadIdx.x; i < R * C; i += blockDim.x) {
        int r = i >> 5, c = i & 31;
        size_t o = (((size_t)l * R + r) * B + b) * C + c;
        split2(tile[c][r], &g_shi[o], &g_slo[o]);
    }
}

__global__ void zeroA_kernel() {
    size_t n16 = (size_t)3 * L * B * D / 8;  // uint4 count
    uint4 z = make_uint4(0, 0, 0, 0);
    for (size_t i = blockIdx.x * blockDim.x + threadIdx.x; i < n16;
         i += (size_t)gridDim.x * blockDim.x) {
        ((uint4*)g_Ahi)[i] = z;
        ((uint4*)g_Alo)[i] = z;
    }
}

// ---------------------------------------------------------------------------
// K1: CTA = (cell, bt in {0,1} -> 64 batch rows, ch in 0..7 -> 128 gate cols).
__global__ void __launch_bounds__(256)
gates_kernel(int d, int lmin) {
    extern __shared__ __nv_bfloat16 sm[];
    const int bx = blockIdx.x;
    const int cell = bx >> 4, sub = bx & 15;
    const int bt = sub & 1, ch = sub >> 1;
    const int l = lmin + cell, r = d - l;
    const int tid = threadIdx.x, warp = tid >> 5, lane = tid & 31;
    const int g = lane >> 2, tig = lane & 3;
    const int row = tid >> 2, q = tid & 3;
    const long abase = (((long)(d % 3) * L + l) * B + bt * 64) * D;
    const long sbase = (((long)l * R + r) * B + bt * 64) * C;
    const long wbase = (long)(ch * 128) * D;

    auto stage = [&](int kb) {
        __nv_bfloat16* st = sm + (kb & 1) * K1_ST;
        const __nv_bfloat16 *ah, *al;
        if (kb < 12) {
            long o = abase + (long)row * D + kb * 32 + q * 8;
            ah = g_Ahi + o; al = g_Alo + o;
        } else {
            long o = sbase + row * C + q * 8;
            ah = g_shi + o; al = g_slo + o;
        }
        cpa(st + row * BP + q * 8, ah);
        cpa(st + K1_A + row * BP + q * 8, al);
        long wo = wbase + (long)row * D + kb * 32 + q * 8;
        cpa(st + 2 * K1_A + row * BP + q * 8, g_Whi + wo);
        cpa(st + 2 * K1_A + (row + 64) * BP + q * 8, g_Whi + wo + (long)64 * D);
        cpa(st + 2 * K1_A + K1_W + row * BP + q * 8, g_Wlo + wo);
        cpa(st + 2 * K1_A + K1_W + (row + 64) * BP + q * 8, g_Wlo + wo + (long)64 * D);
    };

    float acc[8][4];
    #pragma unroll
    for (int t = 0; t < 8; ++t)
        #pragma unroll
        for (int e = 0; e < 4; ++e) acc[t][e] = 0.0f;

    stage(0); cp_commit();
    for (int kb = 0; kb < 13; ++kb) {
        if (kb < 12) { stage(kb + 1); cp_commit(); cp_wait<1>(); }
        else cp_wait<0>();
        __syncthreads();
        const __nv_bfloat16* st = sm + (kb & 1) * K1_ST;
        const __nv_bfloat16* sAhi = st;
        const __nv_bfloat16* sAlo = st + K1_A;
        const __nv_bfloat16* sWhi = st + 2 * K1_A;
        const __nv_bfloat16* sWlo = st + 2 * K1_A + K1_W;
        #pragma unroll
        for (int kk = 0; kk < 2; ++kk) {
            int k0 = kk * 16 + 2 * tig;
            unsigned ahi[4][4], alo[4][4];
            #pragma unroll
            for (int mi = 0; mi < 4; ++mi) {
                int rb = (16 * mi + g) * BP + k0;
                ahi[mi][0] = *(const unsigned*)(sAhi + rb);
                ahi[mi][1] = *(const unsigned*)(sAhi + rb + 8 * BP);
                ahi[mi][2] = *(const unsigned*)(sAhi + rb + 8);
                ahi[mi][3] = *(const unsigned*)(sAhi + rb + 8 * BP + 8);
                alo[mi][0] = *(const unsigned*)(sAlo + rb);
                alo[mi][1] = *(const unsigned*)(sAlo + rb + 8 * BP);
                alo[mi][2] = *(const unsigned*)(sAlo + rb + 8);
                alo[mi][3] = *(const unsigned*)(sAlo + rb + 8 * BP + 8);
            }
            #pragma unroll
            for (int ni = 0; ni < 2; ++ni) {
                int rw = (warp * 16 + ni * 8 + g) * BP + k0;
                unsigned bhi[2] = { *(const unsigned*)(sWhi + rw),
                                    *(const unsigned*)(sWhi + rw + 8) };
                unsigned blo[2] = { *(const unsigned*)(sWlo + rw),
                                    *(const unsigned*)(sWlo + rw + 8) };
                #pragma unroll
                for (int mi = 0; mi < 4; ++mi) {
                    mma16816(acc[mi * 2 + ni], ahi[mi], bhi);
                    mma16816(acc[mi * 2 + ni], ahi[mi], blo);
                    mma16816(acc[mi * 2 + ni], alo[mi], bhi);
                }
            }
        }
        __syncthreads();
    }

    // ---- epilogue (whole-CTA-uniform by ch) ----
    const int jb = ch * 128;
    if (ch < 3) {
        // r region: rt = sigmoid(v) * h_cat, h_cat order [hL|hT|hD], A order [hT|hL|hD]
        #pragma unroll
        for (int mi = 0; mi < 4; ++mi)
            #pragma unroll
            for (int ni = 0; ni < 2; ++ni)
                #pragma unroll
                for (int e = 0; e < 4; ++e) {
                    int bl = 16 * mi + g + 8 * (e >> 1);
                    int j = jb + warp * 16 + ni * 8 + 2 * tig + (e & 1);
                    float v = acc[mi * 2 + ni][e] + g_bias[j];
                    float rg = 1.0f / (1.0f + __expf(-v));
                    int pc = (j < 128) ? 128 + j : (j < 256 ? j - 128 : j);
                    long ai = abase + (long)bl * D + pc;
                    float hv = __bfloat162float(g_Ahi[ai]) + __bfloat162float(g_Alo[ai]);
                    long ri = ((long)l * B + bt * 64 + bl) * 384 + j;
                    split2(rg * hv, &g_rthi[ri], &g_rtlo[ri]);
                }
    } else if (ch == 3) {
        #pragma unroll
        for (int mi = 0; mi < 4; ++mi)
            #pragma unroll
            for (int ni = 0; ni < 2; ++ni)
                #pragma unroll
                for (int e = 0; e < 4; ++e) {
                    int bl = 16 * mi + g + 8 * (e >> 1);
                    int j = jb + warp * 16 + ni * 8 + 2 * tig + (e & 1);
                    g_pbuf[((size_t)l * B + bt * 64 + bl) * U + (j - 384)] =
                        acc[mi * 2 + ni][e] + g_bias[j];
                }
    } else {
        #pragma unroll
        for (int mi = 0; mi < 4; ++mi)
            #pragma unroll
            for (int ni = 0; ni < 2; ++ni)
                #pragma unroll
                for (int e = 0; e < 4; ++e) {
                    int bl = 16 * mi + g + 8 * (e >> 1);
                    int j = jb + warp * 16 + ni * 8 + 2 * tig + (e & 1);
                    int jz = j - 512, grp = jz >> 7, u = jz & 127;
                    g_zbuf[(((size_t)l * 4 + grp) * B + bt * 64 + bl) * U + u] =
                        acc[mi * 2 + ni][e] + g_bias[j];
                }
    }
}

// ---------------------------------------------------------------------------
// K2: CTA = (cell, bt in 0..3 -> 32 batch rows). hU GEMM + combine + scatter.
__global__ void __launch_bounds__(256)
combine_kernel(int d, int lmin) {
    extern __shared__ __nv_bfloat16 sm[];
    const int cell = blockIdx.x >> 2, bt = blockIdx.x & 3;
    const int l = lmin + cell, r = d - l;
    const int tid = threadIdx.x, warp = tid >> 5, lane = tid & 31;
    const int g = lane >> 2, tig = lane & 3;
    const int row = tid >> 2, q = tid & 3;
    const long rtbase = ((long)l * B + bt * 32) * 384;

    auto stage = [&](int kb) {
        __nv_bfloat16* st = sm + (kb & 1) * K2_ST;
        if (row < 32)
            cpa(st + row * BP + q * 8, g_rthi + rtbase + (long)row * 384 + kb * 32 + q * 8);
        else
            cpa(st + K2_RT + (row - 32) * BP + q * 8,
                g_rtlo + rtbase + (long)(row - 32) * 384 + kb * 32 + q * 8);
        long wo = (long)row * 384 + kb * 32 + q * 8;
        cpa(st + 2 * K2_RT + row * BP + q * 8, g_WUhi + wo);
        cpa(st + 2 * K2_RT + (row + 64) * BP + q * 8, g_WUhi + wo + (long)64 * 384);
        cpa(st + 2 * K2_RT + K2_W + row * BP + q * 8, g_WUlo + wo);
        cpa(st + 2 * K2_RT + K2_W + (row + 64) * BP + q * 8, g_WUlo + wo + (long)64 * 384);
    };

    float acc[4][4];
    #pragma unroll
    for (int t = 0; t < 4; ++t)
        #pragma unroll
        for (int e = 0; e < 4; ++e) acc[t][e] = 0.0f;

    stage(0); cp_commit();
    for (int kb = 0; kb < 12; ++kb) {
        if (kb < 11) { stage(kb + 1); cp_commit(); cp_wait<1>(); }
        else cp_wait<0>();
        __syncthreads();
        const __nv_bfloat16* st = sm + (kb & 1) * K2_ST;
        const __nv_bfloat16* sRh = st;
        const __nv_bfloat16* sRl = st + K2_RT;
        const __nv_bfloat16* sWh = st + 2 * K2_RT;
        const __nv_bfloat16* sWl = st + 2 * K2_RT + K2_W;
        #pragma unroll
        for (int kk = 0; kk < 2; ++kk) {
            int k0 = kk * 16 + 2 * tig;
            unsigned ahi[2][4], alo[2][4];
            #pragma unroll
            for (int mi = 0; mi < 2; ++mi) {
                int rb = (16 * mi + g) * BP + k0;
                ahi[mi][0] = *(const unsigned*)(sRh + rb);
                ahi[mi][1] = *(const unsigned*)(sRh + rb + 8 * BP);
                ahi[mi][2] = *(const unsigned*)(sRh + rb + 8);
                ahi[mi][3] = *(const unsigned*)(sRh + rb + 8 * BP + 8);
                alo[mi][0] = *(const unsigned*)(sRl + rb);
                alo[mi][1] = *(const unsigned*)(sRl + rb + 8 * BP);
                alo[mi][2] = *(const unsigned*)(sRl + rb + 8);
                alo[mi][3] = *(const unsigned*)(sRl + rb + 8 * BP + 8);
            }
            #pragma unroll
            for (int ni = 0; ni < 2; ++ni) {
                int rw = (warp * 16 + ni * 8 + g) * BP + k0;
                unsigned bhi[2] = { *(const unsigned*)(sWh + rw),
                                    *(const unsigned*)(sWh + rw + 8) };
                unsigned blo[2] = { *(const unsigned*)(sWl + rw),
                                    *(const unsigned*)(sWl + rw + 8) };
                #pragma unroll
                for (int mi = 0; mi < 2; ++mi) {
                    mma16816(acc[mi * 2 + ni], ahi[mi], bhi);
                    mma16816(acc[mi * 2 + ni], ahi[mi], blo);
                    mma16816(acc[mi * 2 + ni], alo[mi], bhi);
                }
            }
        }
        __syncthreads();
    }

    // ---- combine + write h + scatter split(h) into next diagonals' A ----
    const float* hT = (l > 0)          ? g_H[(d + 2) % 3][l - 1] : (const float*)nullptr;
    const float* hL = (r > 0)          ? g_H[(d + 2) % 3][l]     : (const float*)nullptr;
    const float* hD = (l > 0 && r > 0) ? g_H[(d + 1) % 3][l - 1] : (const float*)nullptr;
    float* Hout = g_H[d % 3][l];
    const int nb = (d + 1) % 3, db = (d + 2) % 3;

    #pragma unroll
    for (int mi = 0; mi < 2; ++mi)
        #pragma unroll
        for (int ni = 0; ni < 2; ++ni)
            #pragma unroll
            for (int e = 0; e < 4; ++e) {
                int b = bt * 32 + 16 * mi + g + 8 * (e >> 1);
                int u = warp * 16 + ni * 8 + 2 * tig + (e & 1);
                float hhat = tanhf(g_pbuf[((size_t)l * B + b) * U + u] +
                                   acc[mi * 2 + ni][e]);
                float zi = g_zbuf[(((size_t)l * 4 + 0) * B + b) * U + u];
                float zl = g_zbuf[(((size_t)l * 4 + 1) * B + b) * U + u];
                float zt = g_zbuf[(((size_t)l * 4 + 2) * B + b) * U + u];
                float zd = g_zbuf[(((size_t)l * 4 + 3) * B + b) * U + u];
                float m = fmaxf(fmaxf(zi, zl), fmaxf(zt, zd));
                float ei = __expf(zi - m), el = __expf(zl - m);
                float et = __expf(zt - m), ed = __expf(zd - m);
                int gi = b * U + u;
                float hLv = hL ? hL[gi] : 0.0f;
                float hTv = hT ? hT[gi] : 0.0f;
                float hDv = hD ? hD[gi] : 0.0f;
                float h = (ei * hhat + el * hLv + et * hTv + ed * hDv) /
                          (ei + el + et + ed);
                Hout[gi] = h;
                __nv_bfloat16 hi, lo;
                split2(h, &hi, &lo);
                if (l + 1 < L) {
                    long t = (((long)nb * L + (l + 1)) * B + b) * D + u;   // hT slot
                    g_Ahi[t] = hi; g_Alo[t] = lo;
                }
                if (r + 1 < R) {
                    long t = (((long)nb * L + l) * B + b) * D + 128 + u;   // hL slot
                    g_Ahi[t] = hi; g_Alo[t] = lo;
                }
                if (l + 1 < L && r + 1 < R) {
                    long t = (((long)db * L + (l + 1)) * B + b) * D + 256 + u; // hD slot
                    g_Ahi[t] = hi; g_Alo[t] = lo;
                }
            }
}

// ---------------------------------------------------------------------------
__global__ void out_kernel(float* __restrict__ out) {
    int i = blockIdx.x * blockDim.x + threadIdx.x;
    if (i < B * U) out[i] = g_H[(L + R - 2) % 3][L - 1][i];
}

extern "C" void kernel_launch(void* const* d_in, const int* in_sizes, int n_in,
                              void* d_out, int out_size) {
    const float* inputs = (const float*)d_in[0];
    const float* Wr  = (const float*)d_in[1];
    const float* br  = (const float*)d_in[2];
    const float* Wz  = (const float*)d_in[3];
    const float* bz  = (const float*)d_in[4];
    const float* Wij = (const float*)d_in[5];
    const float* bij = (const float*)d_in[6];
    const float* WU  = (const float*)d_in[7];

    cudaFuncSetAttribute(gates_kernel, cudaFuncAttributeMaxDynamicSharedMemorySize, K1_SMEM);
    cudaFuncSetAttribute(combine_kernel, cudaFuncAttributeMaxDynamicSharedMemorySize, K2_SMEM);

    prep_kernel<<<128, 256>>>(Wr, br, Wz, bz, Wij, bij, WU);
    transpose_kernel<<<dim3(B, L), 256>>>(inputs);
    zeroA_kernel<<<512, 256>>>();

    for (int d = 0; d < L + R - 1; ++d) {
        int lmin = d - (R - 1); if (lmin < 0) lmin = 0;
        int lmax = (d < L - 1) ? d : (L - 1);
        int n = lmax - lmin + 1;
        gates_kernel<<<n * 16, 256, K1_SMEM>>>(d, lmin);
        combine_kernel<<<n * 4, 256, K2_SMEM>>>(d, lmin);
    }
    out_kernel<<<64, 256>>>((float*)d_out);
}